// round 16
// baseline (speedup 1.0000x reference)
#include <cuda_runtime.h>
#include <cuda_bf16.h>
#include <cstdint>
#include <cstddef>

#define BATCH 64
#define SEQT  512
#define DIN   256
#define HDIM  1024
#define DOUT  128
#define GRID  128

#define BLK_H 1152            // halves per published block (2304 B)

typedef unsigned long long u64;

// ---------------- scratch (device globals: allocation-free) ----------------
__device__ __align__(16) static float g_P[(size_t)BATCH * SEQT * HDIM];  // pre buf A
__device__ __align__(16) static float g_P2[(size_t)BATCH * SEQT * HDIM]; // pre buf B
__device__ __align__(16) static float g_S[(size_t)BATCH * SEQT * HDIM];  // layer outputs
__device__ __align__(16) static __nv_bfloat16 g_Hp2[2][(size_t)GRID * BLK_H]; // h blocks
__device__ volatile unsigned g_flags[GRID];   // exchange flags (monotone)
__device__ volatile unsigned g_prog[GRID];    // absolute per-layer progress (reset each layer)

__device__ __forceinline__ uint32_t smem_u32(const void* p) {
    uint32_t a;
    asm("{ .reg .u64 t; cvta.to.shared.u64 t, %1; cvt.u32.u64 %0, t; }" : "=r"(a) : "l"(p));
    return a;
}

// ---------------- mbarrier + TMA bulk helpers ----------------
__device__ __forceinline__ void mbar_init(uint32_t a, uint32_t cnt) {
    asm volatile("mbarrier.init.shared.b64 [%0], %1;" :: "r"(a), "r"(cnt) : "memory");
}
__device__ __forceinline__ void fence_proxy_async_shared() {
    asm volatile("fence.proxy.async.shared::cta;" ::: "memory");
}
__device__ __forceinline__ void mbar_expect_tx(uint32_t a, uint32_t bytes) {
    asm volatile("mbarrier.arrive.expect_tx.shared.b64 _, [%0], %1;"
                 :: "r"(a), "r"(bytes) : "memory");
}
__device__ __forceinline__ void bulk_g2s(uint32_t dst, const void* src,
                                         uint32_t bytes, uint32_t mbar) {
    asm volatile(
        "cp.async.bulk.shared::cta.global.mbarrier::complete_tx::bytes [%0], [%1], %2, [%3];"
        :: "r"(dst), "l"(src), "r"(bytes), "r"(mbar) : "memory");
}
__device__ __forceinline__ void mbar_wait(uint32_t a, uint32_t ph) {
    asm volatile(
        "{\n\t"
        ".reg .pred P;\n\t"
        "W_%=:\n\t"
        "mbarrier.try_wait.parity.acquire.cta.shared::cta.b64 P, [%0], %1;\n\t"
        "@P bra D_%=;\n\t"
        "bra W_%=;\n\t"
        "D_%=:\n\t"
        "}"
        :: "r"(a), "r"(ph) : "memory");
}

// ---------------- bf16 helpers ----------------
__device__ __forceinline__ void bsplit(float f, uint16_t &hi, uint16_t &lo) {
    __nv_bfloat16 h = __float2bfloat16_rn(f);
    float r = f - __bfloat162float(h);
    __nv_bfloat16 l = __float2bfloat16_rn(r);
    hi = *(uint16_t*)&h;
    lo = *(uint16_t*)&l;
}
__device__ __forceinline__ uint32_t pack16(uint16_t a, uint16_t b) {
    return (uint32_t)a | ((uint32_t)b << 16);
}
__device__ __forceinline__ void split2(float x, float y, uint32_t &hp, uint32_t &lp) {
    uint16_t xh, xl, yh, yl;
    bsplit(x, xh, xl); bsplit(y, yh, yl);
    hp = pack16(xh, yh); lp = pack16(xl, yl);
}

// mma.m16n8k16 row.col bf16 -> f32
__device__ __forceinline__ void mma16816(float* d, const uint32_t* a, const uint32_t* b) {
    asm volatile(
        "mma.sync.aligned.m16n8k16.row.col.f32.bf16.bf16.f32 "
        "{%0,%1,%2,%3}, {%4,%5,%6,%7}, {%8,%9}, {%0,%1,%2,%3};"
        : "+f"(d[0]), "+f"(d[1]), "+f"(d[2]), "+f"(d[3])
        : "r"(a[0]), "r"(a[1]), "r"(a[2]), "r"(a[3]), "r"(b[0]), "r"(b[1]));
}

#define PJP 40    // proj smem pitch in halves

// ============================================================================
// Proj body (bf16 3-term split GEMM). A is loaded with __ldcg (L2-coherent):
// in the fused launch A(=S) is written concurrently by scan CTAs, so the
// non-coherent __ldg path is ILLEGAL for it (R15 bug). W/bias stay __ldg.
// If poll==true, waits on g_prog of the source batch group (+acquire fence).
// ============================================================================
__device__ __forceinline__ void proj_body(
    char* smx, int pidx,
    const float* __restrict__ A, const float* __restrict__ W,
    const float* __restrict__ bi, const float* __restrict__ bh,
    float* __restrict__ C, int K, bool poll)
{
    uint16_t* sAh = (uint16_t*)smx;
    uint16_t* sAl = sAh + 128 * PJP;
    uint16_t* sWh = sAl + 128 * PJP;
    uint16_t* sWl = sWh + 128 * PJP;

    const int tid  = threadIdx.x;
    const int warp = tid >> 5;
    const int lane = tid & 31;
    const int wm = warp >> 2;
    const int wn = warp & 3;
    const int lg = lane >> 2;
    const int lt = lane & 3;
    const int tm = pidx >> 3;
    const int tn = pidx & 7;

    if (poll) {
        // rows [tm*128, +128) = batch b=tm>>2, t in [(tm&3)*128, +128)
        const int tneed = ((tm & 3) * 128) + 128;    // need g_prog >= tneed
        const int gb = tm >> 6;                      // scan batch group
        if (tid < 32) {
            while (g_prog[gb * 32 + tid] < (unsigned)tneed) { }
            __threadfence();   // acquire: order S reads after observed flags
        }
        __syncthreads();
    }

    const int row = tid >> 1;
    const int kq  = (tid & 1) * 8;

    const float* Ab = A + (size_t)(tm * 128) * K + (size_t)row * K;
    const float* Wb = W + (size_t)(tn * 128) * K + (size_t)row * K;

    float d[4][4][4];
    #pragma unroll
    for (int mi = 0; mi < 4; mi++)
        #pragma unroll
        for (int ni = 0; ni < 4; ni++)
            #pragma unroll
            for (int r = 0; r < 4; r++) d[mi][ni][r] = 0.f;

    float4 pa0 = __ldcg((const float4*)(Ab + kq));
    float4 pa1 = __ldcg((const float4*)(Ab + kq + 4));
    float4 pw0 = __ldg((const float4*)(Wb + kq));
    float4 pw1 = __ldg((const float4*)(Wb + kq + 4));

    for (int kc = 0; kc < K; kc += 16) {
        {
            uint4 hv, lv;
            split2(pa0.x, pa0.y, hv.x, lv.x); split2(pa0.z, pa0.w, hv.y, lv.y);
            split2(pa1.x, pa1.y, hv.z, lv.z); split2(pa1.z, pa1.w, hv.w, lv.w);
            *(uint4*)&sAh[row * PJP + kq] = hv;
            *(uint4*)&sAl[row * PJP + kq] = lv;
            split2(pw0.x, pw0.y, hv.x, lv.x); split2(pw0.z, pw0.w, hv.y, lv.y);
            split2(pw1.x, pw1.y, hv.z, lv.z); split2(pw1.z, pw1.w, hv.w, lv.w);
            *(uint4*)&sWh[row * PJP + kq] = hv;
            *(uint4*)&sWl[row * PJP + kq] = lv;
        }
        __syncthreads();

        if (kc + 16 < K) {
            pa0 = __ldcg((const float4*)(Ab + kc + 16 + kq));
            pa1 = __ldcg((const float4*)(Ab + kc + 16 + kq + 4));
            pw0 = __ldg((const float4*)(Wb + kc + 16 + kq));
            pw1 = __ldg((const float4*)(Wb + kc + 16 + kq + 4));
        }

        uint32_t afh[4][4], afl[4][4];
        #pragma unroll
        for (int mi = 0; mi < 4; mi++) {
            const int m = wm * 64 + mi * 16;
            afh[mi][0] = *(const uint32_t*)&sAh[(m + lg) * PJP + lt * 2];
            afh[mi][1] = *(const uint32_t*)&sAh[(m + lg + 8) * PJP + lt * 2];
            afh[mi][2] = *(const uint32_t*)&sAh[(m + lg) * PJP + lt * 2 + 8];
            afh[mi][3] = *(const uint32_t*)&sAh[(m + lg + 8) * PJP + lt * 2 + 8];
            afl[mi][0] = *(const uint32_t*)&sAl[(m + lg) * PJP + lt * 2];
            afl[mi][1] = *(const uint32_t*)&sAl[(m + lg + 8) * PJP + lt * 2];
            afl[mi][2] = *(const uint32_t*)&sAl[(m + lg) * PJP + lt * 2 + 8];
            afl[mi][3] = *(const uint32_t*)&sAl[(m + lg + 8) * PJP + lt * 2 + 8];
        }
        uint32_t bfh[4][2], bfl[4][2];
        #pragma unroll
        for (int ni = 0; ni < 4; ni++) {
            const int n = wn * 32 + ni * 8;
            bfh[ni][0] = *(const uint32_t*)&sWh[(n + lg) * PJP + lt * 2];
            bfh[ni][1] = *(const uint32_t*)&sWh[(n + lg) * PJP + lt * 2 + 8];
            bfl[ni][0] = *(const uint32_t*)&sWl[(n + lg) * PJP + lt * 2];
            bfl[ni][1] = *(const uint32_t*)&sWl[(n + lg) * PJP + lt * 2 + 8];
        }

        #pragma unroll
        for (int mi = 0; mi < 4; mi++)
            #pragma unroll
            for (int ni = 0; ni < 4; ni++) {
                mma16816(d[mi][ni], afh[mi], bfh[ni]);
                mma16816(d[mi][ni], afh[mi], bfl[ni]);
                mma16816(d[mi][ni], afl[mi], bfh[ni]);
            }
        __syncthreads();
    }

    #pragma unroll
    for (int ni = 0; ni < 4; ni++) {
        const int n = tn * 128 + wn * 32 + ni * 8 + lt * 2;
        const float2 bv = make_float2(__ldg(bi + n) + __ldg(bh + n),
                                      __ldg(bi + n + 1) + __ldg(bh + n + 1));
        #pragma unroll
        for (int mi = 0; mi < 4; mi++) {
            const int m = tm * 128 + wm * 64 + mi * 16 + lg;
            *(float2*)(C + (size_t)m * HDIM + n) =
                make_float2(d[mi][ni][0] + bv.x, d[mi][ni][1] + bv.y);
            *(float2*)(C + (size_t)(m + 8) * HDIM + n) =
                make_float2(d[mi][ni][2] + bv.x, d[mi][ni][3] + bv.y);
        }
    }
}

// ============================================================================
// Scan body — R13 dataflow scan + g_prog publication.
// ============================================================================
#define SM_SH   0
#define SM_RED  73728
#define SM_MB   (73728 + 16384)
#define SCAN_SMEM_BYTES (73728 + 16384 + 16)   // 90,128 B (>= proj's 40,960)

__device__ __forceinline__ void scan_body(
    char* smx, const float* __restrict__ P, float* __restrict__ S,
    const float* __restrict__ Whh)
{
    uint16_t* sH  = (uint16_t*)(smx + SM_SH);
    float*    red = (float*)(smx + SM_RED);
    const uint32_t mb   = smem_u32(smx + SM_MB);
    const uint32_t sH_a = smem_u32(sH);

    const int tid  = threadIdx.x;
    const int cta  = blockIdx.x;
    const int gbase = cta & ~31;
    const int own  = cta & 31;
    const int b0 = (cta >> 5) * 16;
    const int o0 = own * 32;
    const int warp = tid >> 5;
    const int lane = tid & 31;
    const int kb = warp * 128;
    const int lg = lane >> 2;
    const int lt = lane & 3;

    uint32_t bh[4][8][2], bl[4][8][2];
    #pragma unroll
    for (int nt = 0; nt < 4; nt++) {
        const int n = o0 + nt * 8 + lg;
        #pragma unroll
        for (int ks = 0; ks < 8; ks++) {
            const int kk = kb + ks * 16 + lt * 2;
            const float* wr = Whh + (size_t)n * HDIM + kk;
            const float w0 = __ldg(wr),     w1 = __ldg(wr + 1);
            const float w8 = __ldg(wr + 8), w9 = __ldg(wr + 9);
            uint16_t h0, l0, h1, l1, h8, l8, h9, l9;
            bsplit(w0, h0, l0); bsplit(w1, h1, l1);
            bsplit(w8, h8, l8); bsplit(w9, h9, l9);
            bh[nt][ks][0] = pack16(h0, h1); bh[nt][ks][1] = pack16(h8, h9);
            bl[nt][ks][0] = pack16(l0, l1); bl[nt][ks][1] = pack16(l8, l9);
        }
    }

    if (tid == 0) {
        mbar_init(mb, 1);
        fence_proxy_async_shared();
    }

    const unsigned base = g_flags[cta];

    const int pb = tid >> 4;
    const int po = (tid & 15) * 2;
    const size_t prow = ((size_t)(b0 + pb) * SEQT) * HDIM + o0 + po;
    const int bo = pb * 72 + po;
    uint16_t* ownB[2] = { (uint16_t*)g_Hp2[0] + (size_t)cta * BLK_H,
                          (uint16_t*)g_Hp2[1] + (size_t)cta * BLK_H };
    uint16_t* sOwn = sH + own * BLK_H;

    // t = 0
    {
        const float2 p2 = *(const float2*)(P + prow);
        const float h0 = fmaxf(p2.x, 0.f), h1 = fmaxf(p2.y, 0.f);
        *(float2*)(S + prow) = make_float2(h0, h1);
        uint32_t hp, lp; split2(h0, h1, hp, lp);
        *(uint32_t*)(ownB[0] + bo)      = hp;
        *(uint32_t*)(ownB[0] + bo + 32) = lp;
        *(uint32_t*)(sOwn + bo)         = hp;
        *(uint32_t*)(sOwn + bo + 32)    = lp;
    }
    __syncthreads();
    if (tid == 0) {
        __threadfence();
        g_flags[cta] = base + 1;
        g_prog[cta] = 1;
    }

    for (int t = 1; t < SEQT; t++) {
        const float2 p2 = __ldg((const float2*)(P + prow + (size_t)t * HDIM));
        const int sr = (t - 1) & 1;
        const int sw = t & 1;

        if (warp == 0) {
            if (lane == 0) mbar_expect_tx(mb, 31 * 2304);
            __syncwarp();
            if (lane != own) {
                while (g_flags[gbase + lane] < base + (unsigned)t) { }
                bulk_g2s(sH_a + lane * 2304,
                         (const uint16_t*)g_Hp2[sr] + (size_t)(gbase + lane) * BLK_H,
                         2304, mb);
            }
        }
        mbar_wait(mb, (t - 1) & 1);

        float d[4][4];
        #pragma unroll
        for (int nt = 0; nt < 4; nt++)
            #pragma unroll
            for (int r = 0; r < 4; r++) d[nt][r] = 0.f;

        #pragma unroll
        for (int ks = 0; ks < 8; ks++) {
            const int peer = warp * 4 + (ks >> 1);
            const int c = (ks & 1) * 16 + lt * 2;
            const uint16_t* pB = sH + peer * BLK_H + c;
            uint32_t ahi[4], alo[4];
            ahi[0] = *(const uint32_t*)(pB + lg * 72);
            ahi[1] = *(const uint32_t*)(pB + (lg + 8) * 72);
            ahi[2] = *(const uint32_t*)(pB + lg * 72 + 8);
            ahi[3] = *(const uint32_t*)(pB + (lg + 8) * 72 + 8);
            alo[0] = *(const uint32_t*)(pB + lg * 72 + 32);
            alo[1] = *(const uint32_t*)(pB + (lg + 8) * 72 + 32);
            alo[2] = *(const uint32_t*)(pB + lg * 72 + 40);
            alo[3] = *(const uint32_t*)(pB + (lg + 8) * 72 + 40);
            #pragma unroll
            for (int nt = 0; nt < 4; nt++) {
                mma16816(d[nt], ahi, bh[nt][ks]);
                mma16816(d[nt], ahi, bl[nt][ks]);
                mma16816(d[nt], alo, bh[nt][ks]);
            }
        }

        #pragma unroll
        for (int nt = 0; nt < 4; nt++) {
            const int oc = nt * 8 + lt * 2;
            *(float2*)&red[warp * 512 + lg * 32 + oc]       = make_float2(d[nt][0], d[nt][1]);
            *(float2*)&red[warp * 512 + (lg + 8) * 32 + oc] = make_float2(d[nt][2], d[nt][3]);
        }
        __syncthreads();

        {
            float s0 = 0.f, s1 = 0.f;
            #pragma unroll
            for (int w8 = 0; w8 < 8; w8++) {
                const float2 v = *(const float2*)&red[w8 * 512 + pb * 32 + po];
                s0 += v.x; s1 += v.y;
            }
            const float h0 = fmaxf(s0 + p2.x, 0.f);
            const float h1 = fmaxf(s1 + p2.y, 0.f);
            *(float2*)(S + prow + (size_t)t * HDIM) = make_float2(h0, h1);
            uint32_t hp, lp; split2(h0, h1, hp, lp);
            *(uint32_t*)(ownB[sw] + bo)      = hp;
            *(uint32_t*)(ownB[sw] + bo + 32) = lp;
            *(uint32_t*)(sOwn + bo)          = hp;
            *(uint32_t*)(sOwn + bo + 32)     = lp;
        }
        __syncthreads();
        if (tid == 0) {
            __threadfence();
            g_flags[cta] = base + (unsigned)t + 1;
            g_prog[cta] = (unsigned)t + 1;
        }
    }
}

// ============================================================================
// Kernels
// ============================================================================
__global__ void __launch_bounds__(256, 1) proj2_kernel(
    const float* __restrict__ A, const float* __restrict__ W,
    const float* __restrict__ bi, const float* __restrict__ bh,
    float* __restrict__ C, int K)
{
    extern __shared__ __align__(16) char smx[];
    proj_body(smx, blockIdx.x, A, W, bi, bh, C, K, false);
}

// fused: CTAs [0,128) run the scan of layer L; CTAs [128, 128+2048) run the
// projection of layer L+1 against S as it is produced (poll g_prog).
__global__ void __launch_bounds__(256, 1) fused_kernel(
    const float* __restrict__ P_in, float* __restrict__ S,
    const float* __restrict__ Whh,
    const float* __restrict__ Wih, const float* __restrict__ bi,
    const float* __restrict__ bh, float* __restrict__ P_out)
{
    extern __shared__ __align__(16) char smx[];
    if (blockIdx.x < GRID) {
        scan_body(smx, P_in, S, Whh);
    } else {
        proj_body(smx, blockIdx.x - GRID, S, Wih, bi, bh, P_out, HDIM, true);
    }
}

__global__ void reset_kernel() {
    if (threadIdx.x < GRID) g_prog[threadIdx.x] = 0;
}

// ============================================================================
// FC: out[64][128] = S[:, T-1, :] @ fc_w^T + fc_b
// ============================================================================
__global__ void __launch_bounds__(128) fc_kernel(
    const float* __restrict__ S, const float* __restrict__ fw,
    const float* __restrict__ fb, float* __restrict__ out)
{
    __shared__ __align__(16) float sx[HDIM];
    const int b = blockIdx.x, tid = threadIdx.x;
    const float* xrow = S + ((size_t)b * SEQT + (SEQT - 1)) * HDIM;
    for (int i = tid; i < HDIM / 4; i += 128)
        *(float4*)&sx[i * 4] = __ldcg((const float4*)(xrow + i * 4));
    __syncthreads();
    float acc = 0.f;
    const float* wrow = fw + (size_t)tid * HDIM;
    #pragma unroll 8
    for (int q = 0; q < HDIM / 4; q++) {
        const float4 w4 = __ldg((const float4*)(wrow + q * 4));
        const float4 x4 = *(const float4*)&sx[q * 4];
        acc += w4.x * x4.x + w4.y * x4.y + w4.z * x4.z + w4.w * x4.w;
    }
    out[(size_t)b * DOUT + tid] = acc + __ldg(fb + tid);
}

// ============================================================================
extern "C" void kernel_launch(void* const* d_in, const int* in_sizes, int n_in,
                              void* d_out, int out_size)
{
    const float* x    = (const float*)d_in[0];   // [64,512,256]
    const float* wih0 = (const float*)d_in[1];   // [1024,256]
    const float* wihr = (const float*)d_in[2];   // [2,1024,1024]
    const float* whh  = (const float*)d_in[3];   // [3,1024,1024]
    const float* bih  = (const float*)d_in[4];   // [3,1024]
    const float* bhh  = (const float*)d_in[5];   // [3,1024]
    const float* fcw  = (const float*)d_in[6];   // [128,1024]
    const float* fcb  = (const float*)d_in[7];   // [128]
    float* out = (float*)d_out;                  // [64,128]

    cudaFuncSetAttribute(proj2_kernel, cudaFuncAttributeMaxDynamicSharedMemorySize,
                         SCAN_SMEM_BYTES);
    cudaFuncSetAttribute(fused_kernel, cudaFuncAttributeMaxDynamicSharedMemorySize,
                         SCAN_SMEM_BYTES);

    void *pP = nullptr, *pP2 = nullptr, *pS = nullptr;
    cudaGetSymbolAddress(&pP, g_P);
    cudaGetSymbolAddress(&pP2, g_P2);
    cudaGetSymbolAddress(&pS, g_S);
    float* P0 = (float*)pP;
    float* P1 = (float*)pP2;
    float* Sq = (float*)pS;

    // L0 projection (depends only on x)
    proj2_kernel<<<2048, 256, SCAN_SMEM_BYTES>>>(x, wih0, bih, bhh, P0, DIN);

    // fused: scan L0 || proj of L1 pre-activations (into P1)
    reset_kernel<<<1, 128>>>();
    fused_kernel<<<GRID + 2048, 256, SCAN_SMEM_BYTES>>>(
        P0, Sq, whh,
        wihr, bih + HDIM, bhh + HDIM, P1);

    // fused: scan L1 || proj of L2 pre-activations (into P0)
    reset_kernel<<<1, 128>>>();
    fused_kernel<<<GRID + 2048, 256, SCAN_SMEM_BYTES>>>(
        P1, Sq, whh + (size_t)HDIM * HDIM,
        wihr + (size_t)HDIM * HDIM, bih + 2 * HDIM, bhh + 2 * HDIM, P0);

    // scan L2 only (no trailing projection)
    fused_kernel<<<GRID, 256, SCAN_SMEM_BYTES>>>(
        P0, Sq, whh + 2 * (size_t)HDIM * HDIM,
        wihr, bih, bhh, P1);

    fc_kernel<<<BATCH, 128>>>(Sq, fcw, fcb, out);
}

// round 17
// speedup vs baseline: 1.0535x; 1.0535x over previous
#include <cuda_runtime.h>
#include <cuda_bf16.h>
#include <cstdint>
#include <cstddef>

#define BATCH 64
#define SEQT  512
#define DIN   256
#define HDIM  1024
#define DOUT  128
#define GRID  128
#define PROJW 148             // persistent proj worker CTAs in fused launch

#define BLK_H 1152            // halves per published block (2304 B)

typedef unsigned long long u64;

// ---------------- scratch (device globals: allocation-free) ----------------
__device__ __align__(16) static float g_P[(size_t)BATCH * SEQT * HDIM];  // pre buf A
__device__ __align__(16) static float g_P2[(size_t)BATCH * SEQT * HDIM]; // pre buf B
__device__ __align__(16) static float g_S[(size_t)BATCH * SEQT * HDIM];  // layer outputs
__device__ __align__(16) static __nv_bfloat16 g_Hp2[2][(size_t)GRID * BLK_H]; // h blocks
__device__ volatile unsigned g_flags[GRID];   // exchange flags (monotone)
__device__ volatile unsigned g_prog[GRID];    // absolute per-layer progress (reset per layer)
__device__ unsigned g_ticket;                 // proj tile ticket (reset per layer)

__device__ __forceinline__ uint32_t smem_u32(const void* p) {
    uint32_t a;
    asm("{ .reg .u64 t; cvta.to.shared.u64 t, %1; cvt.u32.u64 %0, t; }" : "=r"(a) : "l"(p));
    return a;
}

// ---------------- mbarrier + TMA bulk helpers ----------------
__device__ __forceinline__ void mbar_init(uint32_t a, uint32_t cnt) {
    asm volatile("mbarrier.init.shared.b64 [%0], %1;" :: "r"(a), "r"(cnt) : "memory");
}
__device__ __forceinline__ void fence_proxy_async_shared() {
    asm volatile("fence.proxy.async.shared::cta;" ::: "memory");
}
__device__ __forceinline__ void mbar_expect_tx(uint32_t a, uint32_t bytes) {
    asm volatile("mbarrier.arrive.expect_tx.shared.b64 _, [%0], %1;"
                 :: "r"(a), "r"(bytes) : "memory");
}
__device__ __forceinline__ void bulk_g2s(uint32_t dst, const void* src,
                                         uint32_t bytes, uint32_t mbar) {
    asm volatile(
        "cp.async.bulk.shared::cta.global.mbarrier::complete_tx::bytes [%0], [%1], %2, [%3];"
        :: "r"(dst), "l"(src), "r"(bytes), "r"(mbar) : "memory");
}
__device__ __forceinline__ void mbar_wait(uint32_t a, uint32_t ph) {
    asm volatile(
        "{\n\t"
        ".reg .pred P;\n\t"
        "W_%=:\n\t"
        "mbarrier.try_wait.parity.acquire.cta.shared::cta.b64 P, [%0], %1;\n\t"
        "@P bra D_%=;\n\t"
        "bra W_%=;\n\t"
        "D_%=:\n\t"
        "}"
        :: "r"(a), "r"(ph) : "memory");
}

// ---------------- bf16 helpers ----------------
__device__ __forceinline__ void bsplit(float f, uint16_t &hi, uint16_t &lo) {
    __nv_bfloat16 h = __float2bfloat16_rn(f);
    float r = f - __bfloat162float(h);
    __nv_bfloat16 l = __float2bfloat16_rn(r);
    hi = *(uint16_t*)&h;
    lo = *(uint16_t*)&l;
}
__device__ __forceinline__ uint32_t pack16(uint16_t a, uint16_t b) {
    return (uint32_t)a | ((uint32_t)b << 16);
}
__device__ __forceinline__ void split2(float x, float y, uint32_t &hp, uint32_t &lp) {
    uint16_t xh, xl, yh, yl;
    bsplit(x, xh, xl); bsplit(y, yh, yl);
    hp = pack16(xh, yh); lp = pack16(xl, yl);
}

// mma.m16n8k16 row.col bf16 -> f32
__device__ __forceinline__ void mma16816(float* d, const uint32_t* a, const uint32_t* b) {
    asm volatile(
        "mma.sync.aligned.m16n8k16.row.col.f32.bf16.bf16.f32 "
        "{%0,%1,%2,%3}, {%4,%5,%6,%7}, {%8,%9}, {%0,%1,%2,%3};"
        : "+f"(d[0]), "+f"(d[1]), "+f"(d[2]), "+f"(d[3])
        : "r"(a[0]), "r"(a[1]), "r"(a[2]), "r"(a[3]), "r"(b[0]), "r"(b[1]));
}

#define PJP 40    // proj smem pitch in halves

// ============================================================================
// Proj tile body (bf16 3-term split GEMM). A loads use __ldcg (L2-coherent,
// legal under concurrent writes by scan CTAs). W/bias stay __ldg (immutable).
// Caller has already ensured the needed S rows are published (poll outside).
// ============================================================================
__device__ __forceinline__ void proj_body(
    char* smx, int pidx,
    const float* __restrict__ A, const float* __restrict__ W,
    const float* __restrict__ bi, const float* __restrict__ bh,
    float* __restrict__ C, int K)
{
    uint16_t* sAh = (uint16_t*)smx;
    uint16_t* sAl = sAh + 128 * PJP;
    uint16_t* sWh = sAl + 128 * PJP;
    uint16_t* sWl = sWh + 128 * PJP;

    const int tid  = threadIdx.x;
    const int warp = tid >> 5;
    const int lane = tid & 31;
    const int wm = warp >> 2;
    const int wn = warp & 3;
    const int lg = lane >> 2;
    const int lt = lane & 3;
    const int tm = pidx >> 3;
    const int tn = pidx & 7;

    const int row = tid >> 1;
    const int kq  = (tid & 1) * 8;

    const float* Ab = A + (size_t)(tm * 128) * K + (size_t)row * K;
    const float* Wb = W + (size_t)(tn * 128) * K + (size_t)row * K;

    float d[4][4][4];
    #pragma unroll
    for (int mi = 0; mi < 4; mi++)
        #pragma unroll
        for (int ni = 0; ni < 4; ni++)
            #pragma unroll
            for (int r = 0; r < 4; r++) d[mi][ni][r] = 0.f;

    float4 pa0 = __ldcg((const float4*)(Ab + kq));
    float4 pa1 = __ldcg((const float4*)(Ab + kq + 4));
    float4 pw0 = __ldg((const float4*)(Wb + kq));
    float4 pw1 = __ldg((const float4*)(Wb + kq + 4));

    for (int kc = 0; kc < K; kc += 16) {
        {
            uint4 hv, lv;
            split2(pa0.x, pa0.y, hv.x, lv.x); split2(pa0.z, pa0.w, hv.y, lv.y);
            split2(pa1.x, pa1.y, hv.z, lv.z); split2(pa1.z, pa1.w, hv.w, lv.w);
            *(uint4*)&sAh[row * PJP + kq] = hv;
            *(uint4*)&sAl[row * PJP + kq] = lv;
            split2(pw0.x, pw0.y, hv.x, lv.x); split2(pw0.z, pw0.w, hv.y, lv.y);
            split2(pw1.x, pw1.y, hv.z, lv.z); split2(pw1.z, pw1.w, hv.w, lv.w);
            *(uint4*)&sWh[row * PJP + kq] = hv;
            *(uint4*)&sWl[row * PJP + kq] = lv;
        }
        __syncthreads();

        if (kc + 16 < K) {
            pa0 = __ldcg((const float4*)(Ab + kc + 16 + kq));
            pa1 = __ldcg((const float4*)(Ab + kc + 16 + kq + 4));
            pw0 = __ldg((const float4*)(Wb + kc + 16 + kq));
            pw1 = __ldg((const float4*)(Wb + kc + 16 + kq + 4));
        }

        uint32_t afh[4][4], afl[4][4];
        #pragma unroll
        for (int mi = 0; mi < 4; mi++) {
            const int m = wm * 64 + mi * 16;
            afh[mi][0] = *(const uint32_t*)&sAh[(m + lg) * PJP + lt * 2];
            afh[mi][1] = *(const uint32_t*)&sAh[(m + lg + 8) * PJP + lt * 2];
            afh[mi][2] = *(const uint32_t*)&sAh[(m + lg) * PJP + lt * 2 + 8];
            afh[mi][3] = *(const uint32_t*)&sAh[(m + lg + 8) * PJP + lt * 2 + 8];
            afl[mi][0] = *(const uint32_t*)&sAl[(m + lg) * PJP + lt * 2];
            afl[mi][1] = *(const uint32_t*)&sAl[(m + lg + 8) * PJP + lt * 2];
            afl[mi][2] = *(const uint32_t*)&sAl[(m + lg) * PJP + lt * 2 + 8];
            afl[mi][3] = *(const uint32_t*)&sAl[(m + lg + 8) * PJP + lt * 2 + 8];
        }
        uint32_t bfh[4][2], bfl[4][2];
        #pragma unroll
        for (int ni = 0; ni < 4; ni++) {
            const int n = wn * 32 + ni * 8;
            bfh[ni][0] = *(const uint32_t*)&sWh[(n + lg) * PJP + lt * 2];
            bfh[ni][1] = *(const uint32_t*)&sWh[(n + lg) * PJP + lt * 2 + 8];
            bfl[ni][0] = *(const uint32_t*)&sWl[(n + lg) * PJP + lt * 2];
            bfl[ni][1] = *(const uint32_t*)&sWl[(n + lg) * PJP + lt * 2 + 8];
        }

        #pragma unroll
        for (int mi = 0; mi < 4; mi++)
            #pragma unroll
            for (int ni = 0; ni < 4; ni++) {
                mma16816(d[mi][ni], afh[mi], bfh[ni]);
                mma16816(d[mi][ni], afh[mi], bfl[ni]);
                mma16816(d[mi][ni], afl[mi], bfh[ni]);
            }
        __syncthreads();
    }

    #pragma unroll
    for (int ni = 0; ni < 4; ni++) {
        const int n = tn * 128 + wn * 32 + ni * 8 + lt * 2;
        const float2 bv = make_float2(__ldg(bi + n) + __ldg(bh + n),
                                      __ldg(bi + n + 1) + __ldg(bh + n + 1));
        #pragma unroll
        for (int mi = 0; mi < 4; mi++) {
            const int m = tm * 128 + wm * 64 + mi * 16 + lg;
            *(float2*)(C + (size_t)m * HDIM + n) =
                make_float2(d[mi][ni][0] + bv.x, d[mi][ni][1] + bv.y);
            *(float2*)(C + (size_t)(m + 8) * HDIM + n) =
                make_float2(d[mi][ni][2] + bv.x, d[mi][ni][3] + bv.y);
        }
    }
}

// ============================================================================
// Scan body — R13 dataflow scan + g_prog publication.
// ============================================================================
#define SM_SH   0
#define SM_RED  73728
#define SM_MB   (73728 + 16384)
#define SCAN_SMEM_BYTES (73728 + 16384 + 16)   // 90,128 B (>= proj's 40,960)

__device__ __forceinline__ void scan_body(
    char* smx, const float* __restrict__ P, float* __restrict__ S,
    const float* __restrict__ Whh)
{
    uint16_t* sH  = (uint16_t*)(smx + SM_SH);
    float*    red = (float*)(smx + SM_RED);
    const uint32_t mb   = smem_u32(smx + SM_MB);
    const uint32_t sH_a = smem_u32(sH);

    const int tid  = threadIdx.x;
    const int cta  = blockIdx.x;
    const int gbase = cta & ~31;
    const int own  = cta & 31;
    const int b0 = (cta >> 5) * 16;
    const int o0 = own * 32;
    const int warp = tid >> 5;
    const int lane = tid & 31;
    const int kb = warp * 128;
    const int lg = lane >> 2;
    const int lt = lane & 3;

    uint32_t bh[4][8][2], bl[4][8][2];
    #pragma unroll
    for (int nt = 0; nt < 4; nt++) {
        const int n = o0 + nt * 8 + lg;
        #pragma unroll
        for (int ks = 0; ks < 8; ks++) {
            const int kk = kb + ks * 16 + lt * 2;
            const float* wr = Whh + (size_t)n * HDIM + kk;
            const float w0 = __ldg(wr),     w1 = __ldg(wr + 1);
            const float w8 = __ldg(wr + 8), w9 = __ldg(wr + 9);
            uint16_t h0, l0, h1, l1, h8, l8, h9, l9;
            bsplit(w0, h0, l0); bsplit(w1, h1, l1);
            bsplit(w8, h8, l8); bsplit(w9, h9, l9);
            bh[nt][ks][0] = pack16(h0, h1); bh[nt][ks][1] = pack16(h8, h9);
            bl[nt][ks][0] = pack16(l0, l1); bl[nt][ks][1] = pack16(l8, l9);
        }
    }

    if (tid == 0) {
        mbar_init(mb, 1);
        fence_proxy_async_shared();
    }

    const unsigned base = g_flags[cta];

    const int pb = tid >> 4;
    const int po = (tid & 15) * 2;
    const size_t prow = ((size_t)(b0 + pb) * SEQT) * HDIM + o0 + po;
    const int bo = pb * 72 + po;
    uint16_t* ownB[2] = { (uint16_t*)g_Hp2[0] + (size_t)cta * BLK_H,
                          (uint16_t*)g_Hp2[1] + (size_t)cta * BLK_H };
    uint16_t* sOwn = sH + own * BLK_H;

    // t = 0
    {
        const float2 p2 = *(const float2*)(P + prow);
        const float h0 = fmaxf(p2.x, 0.f), h1 = fmaxf(p2.y, 0.f);
        *(float2*)(S + prow) = make_float2(h0, h1);
        uint32_t hp, lp; split2(h0, h1, hp, lp);
        *(uint32_t*)(ownB[0] + bo)      = hp;
        *(uint32_t*)(ownB[0] + bo + 32) = lp;
        *(uint32_t*)(sOwn + bo)         = hp;
        *(uint32_t*)(sOwn + bo + 32)    = lp;
    }
    __syncthreads();
    if (tid == 0) {
        __threadfence();
        g_flags[cta] = base + 1;
        g_prog[cta] = 1;
    }

    for (int t = 1; t < SEQT; t++) {
        const float2 p2 = __ldg((const float2*)(P + prow + (size_t)t * HDIM));
        const int sr = (t - 1) & 1;
        const int sw = t & 1;

        if (warp == 0) {
            if (lane == 0) mbar_expect_tx(mb, 31 * 2304);
            __syncwarp();
            if (lane != own) {
                while (g_flags[gbase + lane] < base + (unsigned)t) { }
                bulk_g2s(sH_a + lane * 2304,
                         (const uint16_t*)g_Hp2[sr] + (size_t)(gbase + lane) * BLK_H,
                         2304, mb);
            }
        }
        mbar_wait(mb, (t - 1) & 1);

        float d[4][4];
        #pragma unroll
        for (int nt = 0; nt < 4; nt++)
            #pragma unroll
            for (int r = 0; r < 4; r++) d[nt][r] = 0.f;

        #pragma unroll
        for (int ks = 0; ks < 8; ks++) {
            const int peer = warp * 4 + (ks >> 1);
            const int c = (ks & 1) * 16 + lt * 2;
            const uint16_t* pB = sH + peer * BLK_H + c;
            uint32_t ahi[4], alo[4];
            ahi[0] = *(const uint32_t*)(pB + lg * 72);
            ahi[1] = *(const uint32_t*)(pB + (lg + 8) * 72);
            ahi[2] = *(const uint32_t*)(pB + lg * 72 + 8);
            ahi[3] = *(const uint32_t*)(pB + (lg + 8) * 72 + 8);
            alo[0] = *(const uint32_t*)(pB + lg * 72 + 32);
            alo[1] = *(const uint32_t*)(pB + (lg + 8) * 72 + 32);
            alo[2] = *(const uint32_t*)(pB + lg * 72 + 40);
            alo[3] = *(const uint32_t*)(pB + (lg + 8) * 72 + 40);
            #pragma unroll
            for (int nt = 0; nt < 4; nt++) {
                mma16816(d[nt], ahi, bh[nt][ks]);
                mma16816(d[nt], ahi, bl[nt][ks]);
                mma16816(d[nt], alo, bh[nt][ks]);
            }
        }

        #pragma unroll
        for (int nt = 0; nt < 4; nt++) {
            const int oc = nt * 8 + lt * 2;
            *(float2*)&red[warp * 512 + lg * 32 + oc]       = make_float2(d[nt][0], d[nt][1]);
            *(float2*)&red[warp * 512 + (lg + 8) * 32 + oc] = make_float2(d[nt][2], d[nt][3]);
        }
        __syncthreads();

        {
            float s0 = 0.f, s1 = 0.f;
            #pragma unroll
            for (int w8 = 0; w8 < 8; w8++) {
                const float2 v = *(const float2*)&red[w8 * 512 + pb * 32 + po];
                s0 += v.x; s1 += v.y;
            }
            const float h0 = fmaxf(s0 + p2.x, 0.f);
            const float h1 = fmaxf(s1 + p2.y, 0.f);
            *(float2*)(S + prow + (size_t)t * HDIM) = make_float2(h0, h1);
            uint32_t hp, lp; split2(h0, h1, hp, lp);
            *(uint32_t*)(ownB[sw] + bo)      = hp;
            *(uint32_t*)(ownB[sw] + bo + 32) = lp;
            *(uint32_t*)(sOwn + bo)          = hp;
            *(uint32_t*)(sOwn + bo + 32)     = lp;
        }
        __syncthreads();
        if (tid == 0) {
            __threadfence();
            g_flags[cta] = base + (unsigned)t + 1;
            g_prog[cta] = (unsigned)t + 1;
        }
    }
}

// ============================================================================
// Kernels
// ============================================================================
__global__ void __launch_bounds__(256, 1) proj2_kernel(
    const float* __restrict__ A, const float* __restrict__ W,
    const float* __restrict__ bi, const float* __restrict__ bh,
    float* __restrict__ C, int K)
{
    extern __shared__ __align__(16) char smx[];
    proj_body(smx, blockIdx.x, A, W, bi, bh, C, K);
}

// fused: CTAs [0,128) run scan(L); CTAs [128, 128+PROJW) are persistent proj
// workers pulling t-ordered tickets (tile quarter q needs scan t >= (q+1)*128).
__global__ void __launch_bounds__(256, 1) fused_kernel(
    const float* __restrict__ P_in, float* __restrict__ S,
    const float* __restrict__ Whh,
    const float* __restrict__ Wih, const float* __restrict__ bi,
    const float* __restrict__ bh, float* __restrict__ P_out)
{
    extern __shared__ __align__(16) char smx[];
    if (blockIdx.x < GRID) {
        scan_body(smx, P_in, S, Whh);
        return;
    }
    // persistent proj worker
    __shared__ unsigned s_tk;
    for (;;) {
        __syncthreads();
        if (threadIdx.x == 0) s_tk = atomicAdd(&g_ticket, 1u);
        __syncthreads();
        const unsigned tk = s_tk;
        if (tk >= 2048u) break;
        // t-ordered mapping: quarter q first; tile (q, r) -> tm = (r>>3)*4+q
        const int q = (int)(tk >> 9);
        const int r = (int)(tk & 511);
        const int pidx = (((r >> 3) * 4 + q) << 3) + (r & 7);
        const int tm = pidx >> 3;
        const int tneed = ((tm & 3) * 128) + 128;
        const int gb = tm >> 6;
        if (threadIdx.x < 32) {
            while (g_prog[gb * 32 + threadIdx.x] < (unsigned)tneed) __nanosleep(256);
            __threadfence();   // acquire: order S reads after observed flags
        }
        __syncthreads();
        proj_body(smx, pidx, S, Wih, bi, bh, P_out, HDIM);
    }
}

__global__ void reset_kernel() {
    if (threadIdx.x < GRID) g_prog[threadIdx.x] = 0;
    if (threadIdx.x == 0) g_ticket = 0;
}

// ============================================================================
// FC: out[64][128] = S[:, T-1, :] @ fc_w^T + fc_b
// ============================================================================
__global__ void __launch_bounds__(128) fc_kernel(
    const float* __restrict__ S, const float* __restrict__ fw,
    const float* __restrict__ fb, float* __restrict__ out)
{
    __shared__ __align__(16) float sx[HDIM];
    const int b = blockIdx.x, tid = threadIdx.x;
    const float* xrow = S + ((size_t)b * SEQT + (SEQT - 1)) * HDIM;
    for (int i = tid; i < HDIM / 4; i += 128)
        *(float4*)&sx[i * 4] = __ldcg((const float4*)(xrow + i * 4));
    __syncthreads();
    float acc = 0.f;
    const float* wrow = fw + (size_t)tid * HDIM;
    #pragma unroll 8
    for (int q = 0; q < HDIM / 4; q++) {
        const float4 w4 = __ldg((const float4*)(wrow + q * 4));
        const float4 x4 = *(const float4*)&sx[q * 4];
        acc += w4.x * x4.x + w4.y * x4.y + w4.z * x4.z + w4.w * x4.w;
    }
    out[(size_t)b * DOUT + tid] = acc + __ldg(fb + tid);
}

// ============================================================================
extern "C" void kernel_launch(void* const* d_in, const int* in_sizes, int n_in,
                              void* d_out, int out_size)
{
    const float* x    = (const float*)d_in[0];   // [64,512,256]
    const float* wih0 = (const float*)d_in[1];   // [1024,256]
    const float* wihr = (const float*)d_in[2];   // [2,1024,1024]
    const float* whh  = (const float*)d_in[3];   // [3,1024,1024]
    const float* bih  = (const float*)d_in[4];   // [3,1024]
    const float* bhh  = (const float*)d_in[5];   // [3,1024]
    const float* fcw  = (const float*)d_in[6];   // [128,1024]
    const float* fcb  = (const float*)d_in[7];   // [128]
    float* out = (float*)d_out;                  // [64,128]

    cudaFuncSetAttribute(proj2_kernel, cudaFuncAttributeMaxDynamicSharedMemorySize,
                         SCAN_SMEM_BYTES);
    cudaFuncSetAttribute(fused_kernel, cudaFuncAttributeMaxDynamicSharedMemorySize,
                         SCAN_SMEM_BYTES);

    void *pP = nullptr, *pP2 = nullptr, *pS = nullptr;
    cudaGetSymbolAddress(&pP, g_P);
    cudaGetSymbolAddress(&pP2, g_P2);
    cudaGetSymbolAddress(&pS, g_S);
    float* P0 = (float*)pP;
    float* P1 = (float*)pP2;
    float* Sq = (float*)pS;

    // L0 projection (depends only on x)
    proj2_kernel<<<2048, 256, SCAN_SMEM_BYTES>>>(x, wih0, bih, bhh, P0, DIN);

    // fused: scan L0 || proj of L1 pre-activations (into P1)
    reset_kernel<<<1, 128>>>();
    fused_kernel<<<GRID + PROJW, 256, SCAN_SMEM_BYTES>>>(
        P0, Sq, whh,
        wihr, bih + HDIM, bhh + HDIM, P1);

    // fused: scan L1 || proj of L2 pre-activations (into P0)
    reset_kernel<<<1, 128>>>();
    fused_kernel<<<GRID + PROJW, 256, SCAN_SMEM_BYTES>>>(
        P1, Sq, whh + (size_t)HDIM * HDIM,
        wihr + (size_t)HDIM * HDIM, bih + 2 * HDIM, bhh + 2 * HDIM, P0);

    // scan L2 only (no trailing projection)
    fused_kernel<<<GRID, 256, SCAN_SMEM_BYTES>>>(
        P0, Sq, whh + 2 * (size_t)HDIM * HDIM,
        wihr, bih, bhh, P1);

    fc_kernel<<<BATCH, 128>>>(Sq, fcw, fcb, out);
}